// round 9
// baseline (speedup 1.0000x reference)
#include <cuda_runtime.h>

// Toy force field: f = -grad_p( sum(MLP(p)) ), MLP = 2 -> 8 -> 4 -> 2 with ReLU.
//
// f depends on pos ONLY through 12 ReLU sign bits (m1: 8, m2: 4):
//   f = W1^T ( m1 .* ( -W2^T (m2 .* v) ) ),  v = colsum(W3).
// Full-answer LUT: F[m2<<8 | m1] = (fx, fy), 4096 x float2 = 32KB shared.
//
// Forward uses fma.rn.f32x2 packed over neuron pairs (R6's proven win).
// Backward is ONE LDS.64 (R7's LUT, now combined with the packed forward).

#define NTHREADS 256
#define ILP 4

typedef unsigned long long ull;

__device__ __forceinline__ ull pack2(float lo, float hi) {
    ull r;
    asm("mov.b64 %0, {%1, %2};"
        : "=l"(r) : "r"(__float_as_uint(lo)), "r"(__float_as_uint(hi)));
    return r;
}
__device__ __forceinline__ void unpack2(ull v, float& lo, float& hi) {
    unsigned a, b;
    asm("mov.b64 {%0, %1}, %2;" : "=r"(a), "=r"(b) : "l"(v));
    lo = __uint_as_float(a);
    hi = __uint_as_float(b);
}
__device__ __forceinline__ ull ffma2(ull a, ull b, ull c) {
    ull d;
    asm("fma.rn.f32x2 %0, %1, %2, %3;" : "=l"(d) : "l"(a), "l"(b), "l"(c));
    return d;
}
__device__ __forceinline__ ull fmul2(ull a, ull b) {
    ull d;
    asm("mul.rn.f32x2 %0, %1, %2;" : "=l"(d) : "l"(a), "l"(b));
    return d;
}

__global__ __launch_bounds__(NTHREADS, 2) void toy_force_kernel(
    const float4* __restrict__ pos4,
    const float*  __restrict__ W1g,
    const float*  __restrict__ b1g,
    const float*  __restrict__ W2g,
    const float*  __restrict__ b2g,
    const float*  __restrict__ W3g,
    float4*       __restrict__ out4,
    int npairs)
{
    __shared__ float sW1[16];
    __shared__ float sb1[8];
    __shared__ float sW2[32];
    __shared__ float sb2[4];
    __shared__ float sv[4];
    __shared__ __align__(8) float2 F[4096];   // F[m2*256 + m1] = (fx, fy)

    const int t = threadIdx.x;

    // Stage raw weights into shared.
    if (t < 16)               sW1[t]      = W1g[t];
    else if (t < 24)          sb1[t - 16] = b1g[t - 16];
    else if (t < 56)          sW2[t - 24] = W2g[t - 24];
    else if (t < 60)          sb2[t - 56] = b2g[t - 56];
    else if (t < 64)          sv[t - 60]  = W3g[t - 60] + W3g[4 + (t - 60)];
    __syncthreads();

    // ---- Build the full force LUT: 16 entries per thread ----
    // Thread t owns m2 = t & 15 and m1's high nibble = t >> 4.
    {
        const int m2  = t & 15;
        const int mhi = t >> 4;

        // g[j] = -(sum_k m2_k * v[k] * W2[k][j])
        float g[8];
#pragma unroll
        for (int j = 0; j < 8; j++) {
            float a = 0.f;
#pragma unroll
            for (int k = 0; k < 4; k++)
                if (m2 & (1 << k)) a += sv[k] * sW2[k * 8 + j];
            g[j] = -a;
        }

        // Partial force from m1's high nibble (neurons 4..7).
        float phx = 0.f, phy = 0.f;
#pragma unroll
        for (int jj = 0; jj < 4; jj++) {
            if (mhi & (1 << jj)) {
                phx += g[4 + jj] * sW1[2 * (4 + jj)];
                phy += g[4 + jj] * sW1[2 * (4 + jj) + 1];
            }
        }

        // Sweep m1's low nibble.
#pragma unroll
        for (int mlo = 0; mlo < 16; mlo++) {
            float fx = phx, fy = phy;
#pragma unroll
            for (int jj = 0; jj < 4; jj++) {
                if (mlo & (1 << jj)) {
                    fx += g[jj] * sW1[2 * jj];
                    fy += g[jj] * sW1[2 * jj + 1];
                }
            }
            F[(m2 << 8) | (mhi << 4) | mlo] = make_float2(fx, fy);
        }
    }
    __syncthreads();

    // ---- Packed per-thread forward weights ----
    ull W10_2[4], W11_2[4], b1_2[4], W2_2[4][4];
    float nb2[4];
#pragma unroll
    for (int jj = 0; jj < 4; jj++) {
        W10_2[jj] = pack2(sW1[4 * jj],     sW1[4 * jj + 2]);  // W1[2jj][0], W1[2jj+1][0]
        W11_2[jj] = pack2(sW1[4 * jj + 1], sW1[4 * jj + 3]);  // W1[2jj][1], W1[2jj+1][1]
        b1_2[jj]  = pack2(sb1[2 * jj],     sb1[2 * jj + 1]);
    }
#pragma unroll
    for (int k = 0; k < 4; k++) {
        nb2[k] = -sb2[k];
#pragma unroll
        for (int jj = 0; jj < 4; jj++)
            W2_2[k][jj] = pack2(sW2[8 * k + 2 * jj], sW2[8 * k + 2 * jj + 1]);
    }

    const int TOT = gridDim.x * blockDim.x;
    const int i0  = blockIdx.x * blockDim.x + t;

    // Batched independent loads (MLP = ILP).
    float4 p[ILP];
    bool ok[ILP];
#pragma unroll
    for (int u = 0; u < ILP; u++) {
        const int i = i0 + u * TOT;
        ok[u] = (i < npairs);
        if (ok[u]) p[u] = pos4[i];
    }

#pragma unroll
    for (int u = 0; u < ILP; u++) {
        if (!ok[u]) continue;
        float fo[4];
#pragma unroll
        for (int s = 0; s < 2; s++) {
            const float x = s ? p[u].z : p[u].x;
            const float y = s ? p[u].w : p[u].y;
            const ull xx = pack2(x, x);
            const ull yy = pack2(y, y);

            // Layer 1 (packed over neuron pairs) + m1 bits + relu
            ull h1_2[4];
            int m1 = 0;
#pragma unroll
            for (int jj = 0; jj < 4; jj++) {
                ull h = ffma2(xx, W10_2[jj], ffma2(yy, W11_2[jj], b1_2[jj]));
                float lo, hi;
                unpack2(h, lo, hi);
                m1 |= (lo > 0.f) ? (1 << (2 * jj))     : 0;
                m1 |= (hi > 0.f) ? (1 << (2 * jj + 1)) : 0;
                h1_2[jj] = pack2(fmaxf(lo, 0.f), fmaxf(hi, 0.f));
            }

            // Layer 2 (packed): only signs needed; bias folded into threshold.
            int m2 = 0;
#pragma unroll
            for (int k = 0; k < 4; k++) {
                ull acc = fmul2(h1_2[0], W2_2[k][0]);
                acc = ffma2(h1_2[1], W2_2[k][1], acc);
                acc = ffma2(h1_2[2], W2_2[k][2], acc);
                acc = ffma2(h1_2[3], W2_2[k][3], acc);
                float lo, hi;
                unpack2(acc, lo, hi);
                m2 |= ((lo + hi) > nb2[k]) ? (256 << k) : 0;
            }

            // The answer is a single LDS.64.
            const float2 f = F[m2 | m1];
            fo[2 * s]     = f.x;
            fo[2 * s + 1] = f.y;
        }
        out4[i0 + u * TOT] = make_float4(fo[0], fo[1], fo[2], fo[3]);
    }
}

extern "C" void kernel_launch(void* const* d_in, const int* in_sizes, int n_in,
                              void* d_out, int out_size) {
    const float4* pos4 = (const float4*)d_in[0];
    const float*  W1   = (const float*)d_in[1];
    const float*  b1   = (const float*)d_in[2];
    const float*  W2   = (const float*)d_in[3];
    const float*  b2   = (const float*)d_in[4];
    const float*  W3   = (const float*)d_in[5];
    float4*       out4 = (float4*)d_out;

    const int npairs = in_sizes[0] / 4;   // floats -> float4 count (2 samples each)
    int grid = (npairs + NTHREADS * ILP - 1) / (NTHREADS * ILP);
    if (grid < 1) grid = 1;

    toy_force_kernel<<<grid, NTHREADS>>>(pos4, W1, b1, W2, b2, W3, out4, npairs);
}

// round 11
// speedup vs baseline: 1.3661x; 1.3661x over previous
#include <cuda_runtime.h>

// Toy force field: f = -grad_p( sum(MLP(p)) ), MLP = 2 -> 8 -> 4 -> 2 with ReLU.
//   f = W1^T ( m1 .* ( W2^T (m2 .* (-v)) ) ),  v = colsum(W3).
// This version computes the backward ARITHMETICALLY (SEL + FFMA2), with zero
// shared-memory accesses in the hot loop: data-dependent smem gathers were the
// issue-rate cap (MIO replays from bank conflicts) in every previous round.

#define NTHREADS 256
#define ILP 4

typedef unsigned long long ull;

__device__ __forceinline__ ull pack2(float lo, float hi) {
    ull r;
    asm("mov.b64 %0, {%1, %2};"
        : "=l"(r) : "r"(__float_as_uint(lo)), "r"(__float_as_uint(hi)));
    return r;
}
__device__ __forceinline__ void unpack2(ull v, float& lo, float& hi) {
    unsigned a, b;
    asm("mov.b64 {%0, %1}, %2;" : "=r"(a), "=r"(b) : "l"(v));
    lo = __uint_as_float(a);
    hi = __uint_as_float(b);
}
__device__ __forceinline__ ull ffma2(ull a, ull b, ull c) {
    ull d;
    asm("fma.rn.f32x2 %0, %1, %2, %3;" : "=l"(d) : "l"(a), "l"(b), "l"(c));
    return d;
}
__device__ __forceinline__ ull fmul2(ull a, ull b) {
    ull d;
    asm("mul.rn.f32x2 %0, %1, %2;" : "=l"(d) : "l"(a), "l"(b));
    return d;
}

__global__ __launch_bounds__(NTHREADS, 2) void toy_force_kernel(
    const float4* __restrict__ pos4,
    const float*  __restrict__ W1g,
    const float*  __restrict__ b1g,
    const float*  __restrict__ W2g,
    const float*  __restrict__ b2g,
    const float*  __restrict__ W3g,
    float4*       __restrict__ out4,
    int npairs)
{
    __shared__ float sW1[16];
    __shared__ float sb1[8];
    __shared__ float sW2[32];
    __shared__ float sb2[4];
    __shared__ float sv[4];     // -colsum(W3): negation baked in here

    const int t = threadIdx.x;

    if (t < 16)               sW1[t]      = W1g[t];
    else if (t < 24)          sb1[t - 16] = b1g[t - 16];
    else if (t < 56)          sW2[t - 24] = W2g[t - 24];
    else if (t < 60)          sb2[t - 56] = b2g[t - 56];
    else if (t < 64)          sv[t - 60]  = -(W3g[t - 60] + W3g[4 + (t - 60)]);
    __syncthreads();

    // ---- Packed per-thread weights (registers; no smem in the hot loop) ----
    ull W10_2[4], W11_2[4], b1_2[4], W2_2[4][4];
    float w10[8], w11[8], nb2[4], nv[4];
#pragma unroll
    for (int jj = 0; jj < 4; jj++) {
        W10_2[jj] = pack2(sW1[4 * jj],     sW1[4 * jj + 2]);  // W1[2jj][0], W1[2jj+1][0]
        W11_2[jj] = pack2(sW1[4 * jj + 1], sW1[4 * jj + 3]);  // W1[2jj][1], W1[2jj+1][1]
        b1_2[jj]  = pack2(sb1[2 * jj],     sb1[2 * jj + 1]);
    }
#pragma unroll
    for (int j = 0; j < 8; j++) { w10[j] = sW1[2 * j]; w11[j] = sW1[2 * j + 1]; }
#pragma unroll
    for (int k = 0; k < 4; k++) {
        nb2[k] = -sb2[k];
        nv[k]  = sv[k];   // already negated
#pragma unroll
        for (int jj = 0; jj < 4; jj++)
            W2_2[k][jj] = pack2(sW2[8 * k + 2 * jj], sW2[8 * k + 2 * jj + 1]);
    }

    const int TOT = gridDim.x * blockDim.x;
    const int i0  = blockIdx.x * blockDim.x + t;

    // Batched independent loads (MLP = ILP).
    float4 p[ILP];
    bool ok[ILP];
#pragma unroll
    for (int u = 0; u < ILP; u++) {
        const int i = i0 + u * TOT;
        ok[u] = (i < npairs);
        if (ok[u]) p[u] = pos4[i];
    }

#pragma unroll
    for (int u = 0; u < ILP; u++) {
        if (!ok[u]) continue;
        float fo[4];
#pragma unroll
        for (int s = 0; s < 2; s++) {
            const float x = s ? p[u].z : p[u].x;
            const float y = s ? p[u].w : p[u].y;
            const ull xx = pack2(x, x);
            const ull yy = pack2(y, y);

            // ---- Layer 1 (packed): pre-activations + relu ----
            float h1p[8];
            ull h1_2[4];
#pragma unroll
            for (int jj = 0; jj < 4; jj++) {
                ull h = ffma2(xx, W10_2[jj], ffma2(yy, W11_2[jj], b1_2[jj]));
                float lo, hi;
                unpack2(h, lo, hi);
                h1p[2 * jj]     = lo;
                h1p[2 * jj + 1] = hi;
                h1_2[jj] = pack2(fmaxf(lo, 0.f), fmaxf(hi, 0.f));
            }

            // ---- Layer 2 (packed): sign only; bias folded into threshold ----
            // u_k = (h2p_k > 0) ? -v_k : 0   (pred-as-data SEL, no branches)
            ull u2[4];
#pragma unroll
            for (int k = 0; k < 4; k++) {
                ull acc = fmul2(h1_2[0], W2_2[k][0]);
                acc = ffma2(h1_2[1], W2_2[k][1], acc);
                acc = ffma2(h1_2[2], W2_2[k][2], acc);
                acc = ffma2(h1_2[3], W2_2[k][3], acc);
                float lo, hi;
                unpack2(acc, lo, hi);
                const float uk = ((lo + hi) > nb2[k]) ? nv[k] : 0.f;
                u2[k] = pack2(uk, uk);
            }

            // ---- Backward, arithmetic: w = W2^T u  (packed over j-pairs) ----
            float wj[8];
#pragma unroll
            for (int jj = 0; jj < 4; jj++) {
                ull w = fmul2(u2[0], W2_2[0][jj]);
                w = ffma2(u2[1], W2_2[1][jj], w);
                w = ffma2(u2[2], W2_2[2][jj], w);
                w = ffma2(u2[3], W2_2[3][jj], w);
                unpack2(w, wj[2 * jj], wj[2 * jj + 1]);
            }

            // ---- f = W1^T (m1 .* w): SEL mask + two independent FFMA chains ----
            float fx = 0.f, fy = 0.f;
#pragma unroll
            for (int j = 0; j < 8; j++) {
                const float wm = (h1p[j] > 0.f) ? wj[j] : 0.f;
                fx = fmaf(wm, w10[j], fx);
                fy = fmaf(wm, w11[j], fy);
            }
            fo[2 * s]     = fx;
            fo[2 * s + 1] = fy;
        }
        out4[i0 + u * TOT] = make_float4(fo[0], fo[1], fo[2], fo[3]);
    }
}

extern "C" void kernel_launch(void* const* d_in, const int* in_sizes, int n_in,
                              void* d_out, int out_size) {
    const float4* pos4 = (const float4*)d_in[0];
    const float*  W1   = (const float*)d_in[1];
    const float*  b1   = (const float*)d_in[2];
    const float*  W2   = (const float*)d_in[3];
    const float*  b2   = (const float*)d_in[4];
    const float*  W3   = (const float*)d_in[5];
    float4*       out4 = (float4*)d_out;

    const int npairs = in_sizes[0] / 4;   // floats -> float4 count (2 samples each)
    int grid = (npairs + NTHREADS * ILP - 1) / (NTHREADS * ILP);
    if (grid < 1) grid = 1;

    toy_force_kernel<<<grid, NTHREADS>>>(pos4, W1, b1, W2, b2, W3, out4, npairs);
}